// round 12
// baseline (speedup 1.0000x reference)
#include <cuda_runtime.h>
#include <cstdint>

#define Hq 128
#define BLq 2048
#define HHq 16384

// ---------------- scratch ----------------
__device__ float g_qln[BLq*Hq];
__device__ float g_Q  [BLq*Hq];
__device__ float g_K  [BLq*Hq];
__device__ float g_V  [BLq*Hq];
__device__ float g_u  [BLq*4*Hq];
__device__ float g_qk [BLq*4*256];
__device__ float g_att[BLq*Hq];
__device__ float g_x  [BLq*Hq];

// ---------------- helpers ----------------
__device__ __forceinline__ void cpa16(float* s, const float* g){
    unsigned sa = (unsigned)__cvta_generic_to_shared(s);
    asm volatile("cp.async.cg.shared.global [%0], [%1], 16;\n" :: "r"(sa), "l"(g));
}
__device__ __forceinline__ void ffma2(unsigned long long &acc, unsigned long long a, unsigned long long b){
    asm("fma.rn.f32x2 %0, %1, %2, %0;" : "+l"(acc) : "l"(a), "l"(b));
}
__device__ __forceinline__ float ullsum(unsigned long long v){
    float lo,hi; asm("mov.b64 {%0,%1}, %2;" : "=f"(lo), "=f"(hi) : "l"(v));
    return lo+hi;
}
__device__ __forceinline__ unsigned long long dup2(float a){
    unsigned long long r; asm("mov.b64 %0, {%1,%1};" : "=l"(r) : "f"(a)); return r;
}
__device__ __forceinline__ void unp2(unsigned long long v, float &a, float &b){
    asm("mov.b64 {%0,%1}, %2;" : "=f"(a), "=f"(b) : "l"(v));
}

// per-warp LN of one 128-float smem row (writes back; optional global copy)
__device__ __forceinline__ void lnrow(float* row, const float* __restrict__ g,
                                      const float* __restrict__ bb, int l,
                                      float* __restrict__ gout){
    float v0=row[l], v1=row[l+32], v2=row[l+64], v3=row[l+96];
    float s  = v0+v1+v2+v3;
    float s2 = v0*v0+v1*v1+v2*v2+v3*v3;
    #pragma unroll
    for(int o=16;o;o>>=1){
        s  += __shfl_xor_sync(0xffffffffu, s , o);
        s2 += __shfl_xor_sync(0xffffffffu, s2, o);
    }
    float m   = s * (1.0f/128.0f);
    float inv = rsqrtf(s2*(1.0f/128.0f) - m*m + 1e-8f);
    float o0 = (v0-m)*inv*g[l]    + bb[l];
    float o1 = (v1-m)*inv*g[l+32] + bb[l+32];
    float o2 = (v2-m)*inv*g[l+64] + bb[l+64];
    float o3 = (v3-m)*inv*g[l+96] + bb[l+96];
    row[l]=o0; row[l+32]=o1; row[l+64]=o2; row[l+96]=o3;
    if(gout){ gout[l]=o0; gout[l+32]=o1; gout[l+64]=o2; gout[l+96]=o3; }
}

// ---- gemmv3: out[r0..r0+16][e] = bias[e] + xin @ W[e,:]^T, 512 threads ----
__device__ __forceinline__ void gemmv3(const float (*xin)[128], float* ws,
                                       const float* __restrict__ W,
                                       const float* __restrict__ bias,
                                       int t, int e, int rg, float out[4]){
    unsigned long long acc[4];
    #pragma unroll
    for(int r=0;r<4;r++) acc[r]=0ULL;
    int sw = e&7;
    #pragma unroll
    for(int s=0;s<4;s++){
        __syncthreads();
        #pragma unroll
        for(int k=0;k<2;k++){
            int idx = t + k*512;
            int ee = idx>>3, c4 = idx&7;
            float4 v = *(const float4*)(W + (size_t)ee*128 + s*32 + c4*4);
            *(float4*)(ws + ee*32 + ((c4 ^ (ee&7))<<2)) = v;
        }
        __syncthreads();
        #pragma unroll
        for(int cq=0;cq<8;cq++){
            ulonglong2 wv = *(const ulonglong2*)(ws + e*32 + ((cq ^ sw)<<2));
            #pragma unroll
            for(int r=0;r<4;r++){
                ulonglong2 xv = *(const ulonglong2*)(&xin[rg*4+r][s*32 + cq*4]);
                ffma2(acc[r], wv.x, xv.x);
                ffma2(acc[r], wv.y, xv.y);
            }
        }
    }
    float be = bias[e];
    #pragma unroll
    for(int r=0;r<4;r++) out[r] = ullsum(acc[r]) + be;
}

// ---------------- k_proj: LN1 + Q,K,V + u = WA1_h^T Q_h ----------------
__global__ void __launch_bounds__(512) k_proj(
    const float* __restrict__ xin,
    const float* __restrict__ g1, const float* __restrict__ b1,
    const float* __restrict__ Wq, const float* __restrict__ bq,
    const float* __restrict__ Wk, const float* __restrict__ bk,
    const float* __restrict__ Wv, const float* __restrict__ bv,
    const float* __restrict__ Wa1,
    float* __restrict__ qlno,
    float* __restrict__ Qo, float* __restrict__ Ko, float* __restrict__ Vo,
    float* __restrict__ uo)
{
    __shared__ float xs[16][128];
    __shared__ float Qs[16][128];
    __shared__ float ws[4096];
    int t = threadIdx.x; int e = t&127; int rg = t>>7; int l = t&31; int w = t>>5;
    int r0 = blockIdx.x*16;
    for(int k=t;k<2048;k+=512) xs[k>>7][k&127] = xin[(size_t)r0*Hq + k];
    __syncthreads();
    lnrow(xs[w], g1, b1, l, qlno + (size_t)(r0+w)*Hq);

    float o4[4];
    gemmv3(xs, ws, Wq, bq, t, e, rg, o4);
    #pragma unroll
    for(int r=0;r<4;r++){
        int rr = rg*4+r;
        Qo[(size_t)(r0+rr)*Hq+e]=o4[r]; Qs[rr][e]=o4[r];
    }
    gemmv3(xs, ws, Wk, bk, t, e, rg, o4);
    #pragma unroll
    for(int r=0;r<4;r++) Ko[(size_t)(r0+rg*4+r)*Hq+e]=o4[r];
    gemmv3(xs, ws, Wv, bv, t, e, rg, o4);
    #pragma unroll
    for(int r=0;r<4;r++) Vo[(size_t)(r0+rg*4+r)*Hq+e]=o4[r];
    __syncthreads();

    // u[row][h][c] = sum_d WA1[h*32+d, c] * Q[row, h*32+d];  thread=(h=rg, c=e)
    int h = rg, c = e;
    unsigned long long ua[16];
    #pragma unroll
    for(int r=0;r<16;r++) ua[r]=0ULL;
    const float* wbase = Wa1 + c;
    #pragma unroll 4
    for(int d=0; d<32; d+=2){
        float wa = wbase[(size_t)(h*32+d)*128];
        float wb = wbase[(size_t)(h*32+d+1)*128];
        unsigned long long w2; asm("mov.b64 %0, {%1,%2};" : "=l"(w2) : "f"(wa), "f"(wb));
        #pragma unroll
        for(int r=0;r<16;r++){
            unsigned long long q2 = *(const unsigned long long*)(&Qs[r][h*32+d]);
            ffma2(ua[r], w2, q2);
        }
    }
    #pragma unroll
    for(int r=0;r<16;r++)
        uo[((size_t)(r0+r)*4 + h)*128 + c] = ullsum(ua[r]);
}

// ---------------- k_qk: lower-triangle tiles only ----------------
__global__ void __launch_bounds__(256) k_qk(const float* __restrict__ Qp,
                                            const float* __restrict__ Kp,
                                            float* __restrict__ qko){
    __shared__ float Qsh[64*33];
    __shared__ float Ksh[64*33];
    const int ITt[10]={0,1,1,2,2,2,3,3,3,3};
    const int JTt[10]={0,0,1,0,1,2,0,1,2,3};
    int bid = blockIdx.x;
    int tri = bid%10; int h=(bid/10)&3; int b=bid/40;
    int it = ITt[tri], jt = JTt[tri];
    int t = threadIdx.x;
    int i0 = it*64, j0 = jt*64;
    for(int k=t;k<2048;k+=256){
        int rr=k>>5, dd=k&31;
        Qsh[rr*33+dd] = Qp[((size_t)(b*256+i0+rr))*128 + h*32+dd];
        Ksh[rr*33+dd] = Kp[((size_t)(b*256+j0+rr))*128 + h*32+dd];
    }
    __syncthreads();
    int i4 = (t>>4)<<2, j4 = (t&15)<<2;
    float acc[4][4];
    #pragma unroll
    for(int a=0;a<4;a++)
        #pragma unroll
        for(int bb=0;bb<4;bb++) acc[a][bb]=0.f;
    #pragma unroll 4
    for(int d=0; d<32; d++){
        float q0=Qsh[(i4+0)*33+d], q1=Qsh[(i4+1)*33+d], q2=Qsh[(i4+2)*33+d], q3=Qsh[(i4+3)*33+d];
        float k0=Ksh[(j4+0)*33+d], k1=Ksh[(j4+1)*33+d], k2=Ksh[(j4+2)*33+d], k3=Ksh[(j4+3)*33+d];
        acc[0][0]+=q0*k0; acc[0][1]+=q0*k1; acc[0][2]+=q0*k2; acc[0][3]+=q0*k3;
        acc[1][0]+=q1*k0; acc[1][1]+=q1*k1; acc[1][2]+=q1*k2; acc[1][3]+=q1*k3;
        acc[2][0]+=q2*k0; acc[2][1]+=q2*k1; acc[2][2]+=q2*k2; acc[2][3]+=q2*k3;
        acc[3][0]+=q3*k0; acc[3][1]+=q3*k1; acc[3][2]+=q3*k2; acc[3][3]+=q3*k3;
    }
    #pragma unroll
    for(int ii=0;ii<4;ii++){
        size_t base = ((size_t)(b*256 + i0+i4+ii)*4 + h)*256 + j0 + j4;
        *(float4*)(qko + base) = make_float4(acc[ii][0],acc[ii][1],acc[ii][2],acc[ii][3]);
    }
}

// ------- fused attention v2: 32-row chunks, 3-buffer ring, depth-2 prefetch ----
// floats: buf 3x4096 | qks 3x128 | u 512 | sc_w 128 | spart 128 | sinv 4
#define ATTN_FLOATS (12288 + 384 + 512 + 128 + 128 + 4)
#define ATTN_SMEM (ATTN_FLOATS*4)
__global__ void __launch_bounds__(256,4) k_attn(
    const float* __restrict__ tm,  const float* __restrict__ qln,
    const float* __restrict__ Vp,  const float* __restrict__ up,
    const float* __restrict__ qkg, const unsigned char* __restrict__ msk,
    const float* __restrict__ Wa2, float* __restrict__ xo)
{
    extern __shared__ float sm[];
    float* qks   = sm + 12288;   // 3 x 128
    float* u_s   = sm + 12672;   // 512
    float* sc_w  = sm + 13184;   // 128
    float* spart = sm + 13312;   // 128
    float* sinv  = sm + 13440;   // 4

    int t = threadIdx.x, l = t&31;
    int r = blockIdx.x, b = r>>8;
    int i = 255 - (r&255);               // heavy rows first
    int rr = (b<<8) + i;
    bool rowmask = msk[rr] != 0;
    int nj  = rowmask ? 256 : (i+1);
    int nch = (nj + 31) >> 5;

    const float NEGV = -4294967295.0f;
    const float SCL  = 0.17677669529663689f;

    // roles
    int jD = t>>3, hD = (t>>1)&3, hf = t&1;        // phase A
    int gC = t>>5;                                  // phase C j-quad
    int eO = t&127, jhO = t>>7, hO = (t&127)>>5;    // phase O

    // ---- chunk loader (cp.async into ring buffer) ----
    auto load_chunk = [&](int cc){
        int bi = cc - (cc/3)*3;
        float* dst = sm + bi*4096;
        int j0n = cc<<5;
        int jn = nj - j0n; if(jn>32) jn=32;
        const float* src = tm + (size_t)rr*32768 + (size_t)j0n*128;
        for(int k=t;k<jn*32;k+=256){
            int jr=k>>5, c4=k&31;
            cpa16(dst + jr*128 + ((c4 ^ (jr&7))<<2), src + 4*k);
        }
        if(t<32){
            int hh=t>>3, qi=t&7;
            cpa16(qks + bi*128 + hh*32 + qi*4,
                  qkg + ((size_t)rr*4 + hh)*256 + j0n + qi*4);
        }
        for(int k=t;k<(32-jn)*32;k+=256)
            *(float4*)(dst + (jn+(k>>5))*128 + (k&31)*4) = make_float4(0.f,0.f,0.f,0.f);
    };

    // ---- prologue: u + chunk0 (group0), chunk1 (group1) ----
    if(t < 128) cpa16(u_s + t*4, up + (size_t)rr*512 + t*4);
    load_chunk(0);
    asm volatile("cp.async.commit_group;\n"::);
    if(nch > 1) load_chunk(1);
    asm volatile("cp.async.commit_group;\n"::);

    unsigned long long tacc[4][2];
    #pragma unroll
    for(int a=0;a<4;a++){ tacc[a][0]=0ULL; tacc[a][1]=0ULL; }
    float oacc0 = 0.f, oacc1 = 0.f;
    float s_part = 0.f;

    for(int c=0;c<nch;c++){
        asm volatile("cp.async.wait_group 1;\n"::);   // chunk c complete
        __syncthreads();                               // prev C/O done; buffers safe
        if(c+2 < nch) load_chunk(c+2);
        asm volatile("cp.async.commit_group;\n"::);

        int cb = c - (c/3)*3;
        const float* bufc = sm + cb*4096;
        int j0 = c<<5;

        // ---- phase A: direct dot, thread = (jD, hD, c-half hf) ----
        {
            const float* base = bufc + jD*128;
            int swz = jD&7;
            const float* ub = u_s + hD*128;
            unsigned long long a = 0ULL;
            #pragma unroll
            for(int q=0;q<16;q++){
                int c4 = hf*16 + q;
                ulonglong2 tv = *(const ulonglong2*)(base + ((c4 ^ swz)<<2));
                ulonglong2 uu = *(const ulonglong2*)(ub + c4*4);
                ffma2(a, uu.x, tv.x);
                ffma2(a, uu.y, tv.y);
            }
            float sc = ullsum(a);
            sc += __shfl_xor_sync(0xffffffffu, sc, 1);
            float qv = qks[cb*128 + hD*32 + jD];
            float rv = rowmask ? 0.f : (((j0 + jD) < nj) ? (sc + qv)*SCL : NEGV);
            float ev = __expf(rv);
            if(hf==0){ sc_w[hD*32 + jD] = ev; s_part += ev; }
        }
        __syncthreads();

        // ---- phase C: tacc over j-quad gC at float4-column l ----
        {
            #pragma unroll
            for(int jj=0;jj<4;jj++){
                int j = gC*4 + jj;
                ulonglong2 tv = *(const ulonglong2*)(bufc + j*128 + ((l ^ (j&7))<<2));
                unsigned long long w0=dup2(sc_w[j]),    w1=dup2(sc_w[32+j]);
                unsigned long long w2=dup2(sc_w[64+j]), w3=dup2(sc_w[96+j]);
                ffma2(tacc[0][0],w0,tv.x); ffma2(tacc[0][1],w0,tv.y);
                ffma2(tacc[1][0],w1,tv.x); ffma2(tacc[1][1],w1,tv.y);
                ffma2(tacc[2][0],w2,tv.x); ffma2(tacc[2][1],w2,tv.y);
                ffma2(tacc[3][0],w3,tv.x); ffma2(tacc[3][1],w3,tv.y);
            }
        }
        // ---- phase O: w@V partials; thread (eO, j-half jhO) ----
        {
            const float* Vb = Vp + (((size_t)b<<8) + j0 + jhO*16)*128 + eO;
            const float* wp = sc_w + hO*32 + jhO*16;
            #pragma unroll
            for(int jj=0;jj<8;jj++){
                oacc0 += wp[jj]   * Vb[jj*128];
                oacc1 += wp[8+jj] * Vb[(8+jj)*128];
            }
        }
    }

    // ---- epilogue ----
    __syncthreads();                       // last C/O done; buffers reusable
    float oacc = oacc0 + oacc1;
    float* P   = sm;                       // 8*512 reduction scratch
    float* t_s = sm + 4096;
    float* red = sm + 8192;
    if(hf==0) spart[hD*32 + jD] = s_part;
    if(jhO==1) red[eO] = oacc;
    #pragma unroll
    for(int h=0;h<4;h++){
        float f0,f1,f2,f3;
        unp2(tacc[h][0], f0, f1);
        unp2(tacc[h][1], f2, f3);
        *(float4*)(P + gC*512 + h*128 + l*4) = make_float4(f0,f1,f2,f3);
    }
    __syncthreads();
    if(t<128){
        int w = t>>5;
        float v = spart[w*32 + l];
        #pragma unroll
        for(int o=16;o;o>>=1) v += __shfl_xor_sync(0xffffffffu, v, o);
        if(l==0) sinv[w] = 1.0f / v;
        // raw reduction of t-partials
        int h = t>>5, cq = t&31;
        float4 acc = make_float4(0.f,0.f,0.f,0.f);
        #pragma unroll
        for(int g=0;g<8;g++){
            float4 p = *(const float4*)(P + g*512 + h*128 + cq*4);
            acc.x+=p.x; acc.y+=p.y; acc.z+=p.z; acc.w+=p.w;
        }
        *(float4*)(t_s + h*128 + cq*4) = acc;
    }
    __syncthreads();
    if(t<128){
        float svh = sinv[hO];
        float o = (oacc + red[eO]) * svh;
        const float4* w2 = (const float4*)(Wa2 + (size_t)eO*128);
        const float4* th = (const float4*)(t_s + hO*128);
        float sv = sinv[hO];
        float4 ts_acc = make_float4(0.f,0.f,0.f,0.f);
        #pragma unroll
        for(int cq=0;cq<32;cq++){
            float4 a=w2[cq], tv=th[cq];
            o += (a.x*tv.x + a.y*tv.y + a.z*tv.z + a.w*tv.w) * sv;
            (void)ts_acc;
        }
        (void)svh;
        xo[(size_t)rr*128 + eO] = qln[(size_t)rr*128 + eO] + o;
    }
}

// ------- k_ffn: LN2 + FFN + residual + mask (+ optional fused final LN) -------
__global__ void __launch_bounds__(512) k_ffn(
    const float* __restrict__ attin,
    const float* __restrict__ g2, const float* __restrict__ b2g,
    const float* __restrict__ W1, const float* __restrict__ b1,
    const float* __restrict__ W2, const float* __restrict__ b2,
    const unsigned char* __restrict__ msk, float* __restrict__ xo,
    const float* __restrict__ lnfg, const float* __restrict__ lnfb)
{
    __shared__ float xs[16][128];
    __shared__ float hs[16][128];
    __shared__ float ws[4096];
    int t = threadIdx.x; int e = t&127; int rg = t>>7; int l = t&31; int w = t>>5;
    int r0 = blockIdx.x*16;
    for(int k=t;k<2048;k+=512) xs[k>>7][k&127] = attin[(size_t)r0*Hq + k];
    __syncthreads();
    lnrow(xs[w], g2, b2g, l, (float*)0);

    float o4[4];
    gemmv3(xs, ws, W1, b1, t, e, rg, o4);
    #pragma unroll
    for(int r=0;r<4;r++) hs[rg*4+r][e] = fmaxf(o4[r], 0.f);
    gemmv3(hs, ws, W2, b2, t, e, rg, o4);
    if(lnfg == (const float*)0){
        #pragma unroll
        for(int r=0;r<4;r++){
            int row = r0 + rg*4 + r;
            float kp = msk[row] ? 0.f : 1.f;
            xo[(size_t)row*Hq + e] = (o4[r] + xs[rg*4+r][e]) * kp;
        }
    } else {
        #pragma unroll
        for(int r=0;r<4;r++){
            int rr = rg*4 + r;
            float kp = msk[r0+rr] ? 0.f : 1.f;
            float v = (o4[r] + xs[rr][e]) * kp;
            hs[rr][e] = v;
        }
        __syncthreads();
        lnrow(hs[w], lnfg, lnfb, l, xo + (size_t)(r0+w)*Hq);
    }
}

// ---------------- launch ----------------
extern "C" void kernel_launch(void* const* d_in, const int* in_sizes, int n_in,
                              void* d_out, int out_size){
    const float* seqs = (const float*)d_in[0];
    const unsigned char* msk = (const unsigned char*)d_in[1];
    const float* tm  = (const float*)d_in[2];
    const float* Qw  = (const float*)d_in[3];
    const float* Qb  = (const float*)d_in[4];
    const float* Kw  = (const float*)d_in[5];
    const float* Kb  = (const float*)d_in[6];
    const float* Vw  = (const float*)d_in[7];
    const float* Vb  = (const float*)d_in[8];
    const float* WA1 = (const float*)d_in[9];
    const float* WA2 = (const float*)d_in[10];
    const float* ln1g= (const float*)d_in[11];
    const float* ln1b= (const float*)d_in[12];
    const float* ln2g= (const float*)d_in[13];
    const float* ln2b= (const float*)d_in[14];
    const float* c1w = (const float*)d_in[15];
    const float* c1b = (const float*)d_in[16];
    const float* c2w = (const float*)d_in[17];
    const float* c2b = (const float*)d_in[18];
    const float* lnfg= (const float*)d_in[19];
    const float* lnfb= (const float*)d_in[20];

    float *gqln,*gQ,*gK,*gV,*gu,*gqk,*gatt,*gx;
    cudaGetSymbolAddress((void**)&gqln, g_qln);
    cudaGetSymbolAddress((void**)&gQ,   g_Q);
    cudaGetSymbolAddress((void**)&gK,   g_K);
    cudaGetSymbolAddress((void**)&gV,   g_V);
    cudaGetSymbolAddress((void**)&gu,   g_u);
    cudaGetSymbolAddress((void**)&gqk,  g_qk);
    cudaGetSymbolAddress((void**)&gatt, g_att);
    cudaGetSymbolAddress((void**)&gx,   g_x);

    cudaFuncSetAttribute(k_attn, cudaFuncAttributeMaxDynamicSharedMemorySize, ATTN_SMEM);

    for(int blk=0; blk<2; blk++){
        const float* xin = blk ? (const float*)gx : seqs;
        k_proj<<<128,512>>>(xin, ln1g+blk*Hq, ln1b+blk*Hq,
                            Qw+(size_t)blk*HHq, Qb+blk*Hq,
                            Kw+(size_t)blk*HHq, Kb+blk*Hq,
                            Vw+(size_t)blk*HHq, Vb+blk*Hq,
                            WA1+(size_t)blk*HHq,
                            gqln, gQ, gK, gV, gu);
        k_qk  <<<320,256>>>(gQ, gK, gqk);
        k_attn<<<BLq,256,ATTN_SMEM>>>(tm, gqln, gV, gu, gqk, msk,
                                      WA2+(size_t)blk*HHq, gatt);
        k_ffn <<<128,512>>>(gatt, ln2g+blk*Hq, ln2b+blk*Hq,
                            c1w+(size_t)blk*HHq, c1b+blk*Hq,
                            c2w+(size_t)blk*HHq, c2b+blk*Hq, msk,
                            blk==0 ? gx : (float*)d_out,
                            blk==0 ? (const float*)0 : lnfg,
                            blk==0 ? (const float*)0 : lnfb);
    }
}

// round 13
// speedup vs baseline: 2.3027x; 2.3027x over previous
#include <cuda_runtime.h>
#include <cstdint>

#define Hq 128
#define BLq 2048
#define HHq 16384

// ---------------- scratch ----------------
__device__ float g_qln[BLq*Hq];
__device__ float g_Q  [BLq*Hq];
__device__ float g_K  [BLq*Hq];
__device__ float g_V  [BLq*Hq];
__device__ float g_u  [BLq*4*Hq];
__device__ float g_qk [BLq*4*256];
__device__ float g_att[BLq*Hq];
__device__ float g_x  [BLq*Hq];

// ---------------- helpers ----------------
__device__ __forceinline__ void cpa16(float* s, const float* g){
    unsigned sa = (unsigned)__cvta_generic_to_shared(s);
    asm volatile("cp.async.cg.shared.global [%0], [%1], 16;\n" :: "r"(sa), "l"(g));
}
__device__ __forceinline__ void ffma2(unsigned long long &acc, unsigned long long a, unsigned long long b){
    asm("fma.rn.f32x2 %0, %1, %2, %0;" : "+l"(acc) : "l"(a), "l"(b));
}
__device__ __forceinline__ float ullsum(unsigned long long v){
    float lo,hi; asm("mov.b64 {%0,%1}, %2;" : "=f"(lo), "=f"(hi) : "l"(v));
    return lo+hi;
}
__device__ __forceinline__ unsigned long long dup2(float a){
    unsigned long long r; asm("mov.b64 %0, {%1,%1};" : "=l"(r) : "f"(a)); return r;
}
__device__ __forceinline__ void unp2(unsigned long long v, float &a, float &b){
    asm("mov.b64 {%0,%1}, %2;" : "=f"(a), "=f"(b) : "l"(v));
}

// per-warp LN of one 128-float smem row (writes back; optional global copy)
__device__ __forceinline__ void lnrow(float* row, const float* __restrict__ g,
                                      const float* __restrict__ bb, int l,
                                      float* __restrict__ gout){
    float v0=row[l], v1=row[l+32], v2=row[l+64], v3=row[l+96];
    float s  = v0+v1+v2+v3;
    float s2 = v0*v0+v1*v1+v2*v2+v3*v3;
    #pragma unroll
    for(int o=16;o;o>>=1){
        s  += __shfl_xor_sync(0xffffffffu, s , o);
        s2 += __shfl_xor_sync(0xffffffffu, s2, o);
    }
    float m   = s * (1.0f/128.0f);
    float inv = rsqrtf(s2*(1.0f/128.0f) - m*m + 1e-8f);
    float o0 = (v0-m)*inv*g[l]    + bb[l];
    float o1 = (v1-m)*inv*g[l+32] + bb[l+32];
    float o2 = (v2-m)*inv*g[l+64] + bb[l+64];
    float o3 = (v3-m)*inv*g[l+96] + bb[l+96];
    row[l]=o0; row[l+32]=o1; row[l+64]=o2; row[l+96]=o3;
    if(gout){ gout[l]=o0; gout[l+32]=o1; gout[l+64]=o2; gout[l+96]=o3; }
}

// ---- gemmv4: out[rg*4..+4][e] = bias[e] + xin @ W[e,:]^T, 512 threads ----
// W k-quarters staged via cp.async, double-buffered (ws = 2 x 4096 floats).
__device__ __forceinline__ void gemmv4(const float (*xin)[128], float* ws,
                                       const float* __restrict__ W,
                                       const float* __restrict__ bias,
                                       int t, int e, int rg, float out[4]){
    unsigned long long acc[4];
    #pragma unroll
    for(int r=0;r<4;r++) acc[r]=0ULL;
    int sw = e&7;
    // preload stage 0 into buf 0
    #pragma unroll
    for(int k=0;k<2;k++){
        int idx = t + k*512;
        int ee = idx>>3, c4 = idx&7;
        cpa16(ws + ee*32 + ((c4 ^ (ee&7))<<2), W + (size_t)ee*128 + c4*4);
    }
    asm volatile("cp.async.commit_group;\n"::);
    #pragma unroll
    for(int s=0;s<4;s++){
        if(s+1<4){
            float* wd = ws + ((s+1)&1)*4096;
            #pragma unroll
            for(int k=0;k<2;k++){
                int idx = t + k*512;
                int ee = idx>>3, c4 = idx&7;
                cpa16(wd + ee*32 + ((c4 ^ (ee&7))<<2),
                      W + (size_t)ee*128 + (s+1)*32 + c4*4);
            }
            asm volatile("cp.async.commit_group;\n"::);
            asm volatile("cp.async.wait_group 1;\n"::);
        } else {
            asm volatile("cp.async.wait_group 0;\n"::);
        }
        __syncthreads();
        const float* wsrc = ws + (s&1)*4096;
        #pragma unroll
        for(int cq=0;cq<8;cq++){
            ulonglong2 wv = *(const ulonglong2*)(wsrc + e*32 + ((cq ^ sw)<<2));
            #pragma unroll
            for(int r=0;r<4;r++){
                ulonglong2 xv = *(const ulonglong2*)(&xin[rg*4+r][s*32 + cq*4]);
                ffma2(acc[r], wv.x, xv.x);
                ffma2(acc[r], wv.y, xv.y);
            }
        }
        __syncthreads();
    }
    float be = bias[e];
    #pragma unroll
    for(int r=0;r<4;r++) out[r] = ullsum(acc[r]) + be;
}

// ---------------- k_proj: LN1 + Q,K,V + u = WA1_h^T Q_h ----------------
__global__ void __launch_bounds__(512) k_proj(
    const float* __restrict__ xin,
    const float* __restrict__ g1, const float* __restrict__ b1,
    const float* __restrict__ Wq, const float* __restrict__ bq,
    const float* __restrict__ Wk, const float* __restrict__ bk,
    const float* __restrict__ Wv, const float* __restrict__ bv,
    const float* __restrict__ Wa1,
    float* __restrict__ qlno,
    float* __restrict__ Qo, float* __restrict__ Ko, float* __restrict__ Vo,
    float* __restrict__ uo)
{
    __shared__ float xs[16][128];
    __shared__ float Qs[16][128];
    __shared__ float ws[8192];
    int t = threadIdx.x; int e = t&127; int rg = t>>7; int l = t&31; int w = t>>5;
    int r0 = blockIdx.x*16;
    for(int k=t;k<2048;k+=512) xs[k>>7][k&127] = xin[(size_t)r0*Hq + k];
    __syncthreads();
    lnrow(xs[w], g1, b1, l, qlno + (size_t)(r0+w)*Hq);
    __syncthreads();

    float o4[4];
    gemmv4(xs, ws, Wq, bq, t, e, rg, o4);
    #pragma unroll
    for(int r=0;r<4;r++){
        int rr = rg*4+r;
        Qo[(size_t)(r0+rr)*Hq+e]=o4[r]; Qs[rr][e]=o4[r];
    }
    gemmv4(xs, ws, Wk, bk, t, e, rg, o4);
    #pragma unroll
    for(int r=0;r<4;r++) Ko[(size_t)(r0+rg*4+r)*Hq+e]=o4[r];
    gemmv4(xs, ws, Wv, bv, t, e, rg, o4);
    #pragma unroll
    for(int r=0;r<4;r++) Vo[(size_t)(r0+rg*4+r)*Hq+e]=o4[r];
    __syncthreads();

    // u[row][h][c] = sum_d WA1[h*32+d, c] * Q[row, h*32+d];  thread=(h=rg, c=e)
    int h = rg, c = e;
    unsigned long long ua[16];
    #pragma unroll
    for(int r=0;r<16;r++) ua[r]=0ULL;
    const float* wbase = Wa1 + c;
    #pragma unroll 4
    for(int d=0; d<32; d+=2){
        float wa = wbase[(size_t)(h*32+d)*128];
        float wb = wbase[(size_t)(h*32+d+1)*128];
        unsigned long long w2; asm("mov.b64 %0, {%1,%2};" : "=l"(w2) : "f"(wa), "f"(wb));
        #pragma unroll
        for(int r=0;r<16;r++){
            unsigned long long q2 = *(const unsigned long long*)(&Qs[r][h*32+d]);
            ffma2(ua[r], w2, q2);
        }
    }
    #pragma unroll
    for(int r=0;r<16;r++)
        uo[((size_t)(r0+r)*4 + h)*128 + c] = ullsum(ua[r]);
}

// ---------------- k_qk: lower-triangle tiles only ----------------
__global__ void __launch_bounds__(256) k_qk(const float* __restrict__ Qp,
                                            const float* __restrict__ Kp,
                                            float* __restrict__ qko){
    __shared__ float Qsh[64*33];
    __shared__ float Ksh[64*33];
    const int ITt[10]={0,1,1,2,2,2,3,3,3,3};
    const int JTt[10]={0,0,1,0,1,2,0,1,2,3};
    int bid = blockIdx.x;
    int tri = bid%10; int h=(bid/10)&3; int b=bid/40;
    int it = ITt[tri], jt = JTt[tri];
    int t = threadIdx.x;
    int i0 = it*64, j0 = jt*64;
    for(int k=t;k<2048;k+=256){
        int rr=k>>5, dd=k&31;
        Qsh[rr*33+dd] = Qp[((size_t)(b*256+i0+rr))*128 + h*32+dd];
        Ksh[rr*33+dd] = Kp[((size_t)(b*256+j0+rr))*128 + h*32+dd];
    }
    __syncthreads();
    int i4 = (t>>4)<<2, j4 = (t&15)<<2;
    float acc[4][4];
    #pragma unroll
    for(int a=0;a<4;a++)
        #pragma unroll
        for(int bb=0;bb<4;bb++) acc[a][bb]=0.f;
    #pragma unroll 4
    for(int d=0; d<32; d++){
        float q0=Qsh[(i4+0)*33+d], q1=Qsh[(i4+1)*33+d], q2=Qsh[(i4+2)*33+d], q3=Qsh[(i4+3)*33+d];
        float k0=Ksh[(j4+0)*33+d], k1=Ksh[(j4+1)*33+d], k2=Ksh[(j4+2)*33+d], k3=Ksh[(j4+3)*33+d];
        acc[0][0]+=q0*k0; acc[0][1]+=q0*k1; acc[0][2]+=q0*k2; acc[0][3]+=q0*k3;
        acc[1][0]+=q1*k0; acc[1][1]+=q1*k1; acc[1][2]+=q1*k2; acc[1][3]+=q1*k3;
        acc[2][0]+=q2*k0; acc[2][1]+=q2*k1; acc[2][2]+=q2*k2; acc[2][3]+=q2*k3;
        acc[3][0]+=q3*k0; acc[3][1]+=q3*k1; acc[3][2]+=q3*k2; acc[3][3]+=q3*k3;
    }
    #pragma unroll
    for(int ii=0;ii<4;ii++){
        size_t base = ((size_t)(b*256 + i0+i4+ii)*4 + h)*256 + j0 + j4;
        *(float4*)(qko + base) = make_float4(acc[ii][0],acc[ii][1],acc[ii][2],acc[ii][3]);
    }
}

// ---------------- fused attention, static-max softmax, 64-row chunks ----------
#define ATTN_FLOATS (16384 + 512 + 512 + 1024 + 256 + 4)
#define ATTN_SMEM (ATTN_FLOATS*4)
__global__ void __launch_bounds__(256) k_attn(
    const float* __restrict__ tm,  const float* __restrict__ qln,
    const float* __restrict__ Vp,  const float* __restrict__ up,
    const float* __restrict__ qkg, const unsigned char* __restrict__ msk,
    const float* __restrict__ Wa2, float* __restrict__ xo)
{
    extern __shared__ float sm[];
    float* qks  = sm + 16384;   // 2 x 256
    float* u_s  = sm + 16896;   // 512
    float* s4   = sm + 17408;   // 1024
    float* sc_w = sm + 18432;   // 256
    float* sinv = sm + 18688;
    float* t_s  = s4;           // epilogue reuse
    float* red  = s4 + 512;

    int t = threadIdx.x, l = t&31, w = t>>5;
    int r = blockIdx.x, b = r>>8;
    int i = 255 - (r&255);               // heavy rows first
    int rr = (b<<8) + i;
    bool rowmask = msk[rr] != 0;
    int nj  = rowmask ? 256 : (i+1);
    int nch = (nj + 63) >> 6;

    // ---- prologue: u row + chunk0 tm (swizzled) + chunk0 qk ----
    if(t < 128) cpa16(u_s + t*4, up + (size_t)rr*512 + t*4);
    {
        int jn = nj < 64 ? nj : 64;
        const float* src = tm + (size_t)rr*32768;
        for(int k=t;k<jn*32;k+=256){
            int jr=k>>5, c4=k&31;
            cpa16(sm + jr*128 + ((c4 ^ (jr&7))<<2), src + 4*k);
        }
        if(t<64){
            int hh=t>>4, qi=t&15;
            cpa16(qks + hh*64 + qi*4, qkg + ((size_t)rr*4 + hh)*256 + qi*4);
        }
        for(int k=t;k<(64-jn)*32;k+=256)
            *(float4*)(sm + (jn+(k>>5))*128 + (k&31)*4) = make_float4(0.f,0.f,0.f,0.f);
    }
    asm volatile("cp.async.commit_group;\n"::);

    int qA = t>>6, jA = t&63;            // phase A: c-quarter x j
    int eO = t&127, jhO = t>>7, hO = (t&127)>>5; // phase O: elem x j-half

    unsigned long long tacc[4][2];
    #pragma unroll
    for(int a=0;a<4;a++){ tacc[a][0]=0ULL; tacc[a][1]=0ULL; }
    float oacc0 = 0.f, oacc1 = 0.f;
    float s_run = 0.f;
    const float NEGV = -4294967295.0f;
    const float SCL  = 0.17677669529663689f;

    for(int c=0;c<nch;c++){
        int cb = c&1;
        if(c+1 < nch){
            int nb = cb^1;
            int j0n = (c+1)<<6;
            int jn = nj - j0n; if(jn>64) jn=64;
            const float* src = tm + (size_t)rr*32768 + (size_t)j0n*128;
            float* dst = sm + nb*8192;
            for(int k=t;k<jn*32;k+=256){
                int jr=k>>5, c4=k&31;
                cpa16(dst + jr*128 + ((c4 ^ (jr&7))<<2), src + 4*k);
            }
            if(t<64){
                int hh=t>>4, qi=t&15;
                cpa16(qks + nb*256 + hh*64 + qi*4,
                      qkg + ((size_t)rr*4 + hh)*256 + j0n + qi*4);
            }
            for(int k=t;k<(64-jn)*32;k+=256)
                *(float4*)(dst + (jn+(k>>5))*128 + (k&31)*4) = make_float4(0.f,0.f,0.f,0.f);
            asm volatile("cp.async.commit_group;\n"::);
            asm volatile("cp.async.wait_group 1;\n"::);
        } else {
            asm volatile("cp.async.wait_group 0;\n"::);
        }
        __syncthreads();
        const float* bufc = sm + cb*8192;
        int j0 = c<<6;

        // ---- phase A: packed partial scores over c-quarter qA for row jA ----
        {
            const float* base = bufc + jA*128;
            int sw = jA&7;
            unsigned long long a0=0ULL,a1=0ULL,a2=0ULL,a3=0ULL;
            #pragma unroll
            for(int cq=0;cq<8;cq++){
                int c4 = qA*8+cq;
                ulonglong2 tv = *(const ulonglong2*)(base + ((c4 ^ sw)<<2));
                ulonglong2 u0 = *(const ulonglong2*)(u_s +        c4*4);
                ulonglong2 u1 = *(const ulonglong2*)(u_s + 128 +  c4*4);
                ulonglong2 u2 = *(const ulonglong2*)(u_s + 256 +  c4*4);
                ulonglong2 u3 = *(const ulonglong2*)(u_s + 384 +  c4*4);
                ffma2(a0,u0.x,tv.x); ffma2(a0,u0.y,tv.y);
                ffma2(a1,u1.x,tv.x); ffma2(a1,u1.y,tv.y);
                ffma2(a2,u2.x,tv.x); ffma2(a2,u2.y,tv.y);
                ffma2(a3,u3.x,tv.x); ffma2(a3,u3.y,tv.y);
            }
            s4[(qA*4+0)*64 + jA] = ullsum(a0);
            s4[(qA*4+1)*64 + jA] = ullsum(a1);
            s4[(qA*4+2)*64 + jA] = ullsum(a2);
            s4[(qA*4+3)*64 + jA] = ullsum(a3);
        }
        __syncthreads();

        // ---- phase B: reduce + static-max softmax (warp w = head w) ----
        if(w<4){
            float r0 = (s4[(0*4+w)*64+l] + s4[(1*4+w)*64+l] +
                        s4[(2*4+w)*64+l] + s4[(3*4+w)*64+l] +
                        qks[cb*256 + w*64 + l]) * SCL;
            float r1 = (s4[(0*4+w)*64+32+l] + s4[(1*4+w)*64+32+l] +
                        s4[(2*4+w)*64+32+l] + s4[(3*4+w)*64+32+l] +
                        qks[cb*256 + w*64 + 32 + l]) * SCL;
            r0 = rowmask ? 0.f : (((j0 + l)      < nj) ? r0 : NEGV);
            r1 = rowmask ? 0.f : (((j0 + 32 + l) < nj) ? r1 : NEGV);
            float e0 = __expf(r0), e1 = __expf(r1);
            float cs = e0 + e1;
            #pragma unroll
            for(int o=16;o;o>>=1) cs += __shfl_xor_sync(0xffffffffu,cs,o);
            s_run += cs;
            sc_w[w*64 + l]      = e0;
            sc_w[w*64 + 32 + l] = e1;
        }
        __syncthreads();

        // ---- phase C: packed tacc over j-octant w at float4-column l ----
        {
            #pragma unroll
            for(int jj=0;jj<8;jj++){
                int j = w*8 + jj;
                ulonglong2 tv = *(const ulonglong2*)(bufc + j*128 + ((l ^ jj)<<2));
                unsigned long long w0=dup2(sc_w[j]),   w1=dup2(sc_w[64+j]);
                unsigned long long w2=dup2(sc_w[128+j]),w3=dup2(sc_w[192+j]);
                ffma2(tacc[0][0],w0,tv.x); ffma2(tacc[0][1],w0,tv.y);
                ffma2(tacc[1][0],w1,tv.x); ffma2(tacc[1][1],w1,tv.y);
                ffma2(tacc[2][0],w2,tv.x); ffma2(tacc[2][1],w2,tv.y);
                ffma2(tacc[3][0],w3,tv.x); ffma2(tacc[3][1],w3,tv.y);
            }
        }
        // ---- phase O: w@V partials; thread (eO, j-half jhO) ----
        {
            const float* Vb = Vp + (((size_t)b<<8) + j0 + jhO*32)*128 + eO;
            const float* wp = sc_w + hO*64 + jhO*32;
            #pragma unroll
            for(int jj=0;jj<16;jj++){
                oacc0 += wp[jj]    * Vb[jj*128];
                oacc1 += wp[16+jj] * Vb[(16+jj)*128];
            }
        }
        __syncthreads();
    }

    // ---- epilogue ----
    float oacc = oacc0 + oacc1;
    if(w<4 && l==0) sinv[w] = 1.0f / s_run;
    if(jhO==1) red[eO] = oacc;
    float* P = sm;  // tm buffers dead: 8-way tacc reduction scratch
    #pragma unroll
    for(int h=0;h<4;h++){
        float f0,f1,f2,f3;
        unp2(tacc[h][0], f0, f1);
        unp2(tacc[h][1], f2, f3);
        *(float4*)(P + w*512 + h*128 + l*4) = make_float4(f0,f1,f2,f3);
    }
    __syncthreads();
    if(t<128){
        int h = t>>5, cq = t&31;
        float4 acc = make_float4(0.f,0.f,0.f,0.f);
        #pragma unroll
        for(int g=0;g<8;g++){
            float4 p = *(const float4*)(P + g*512 + h*128 + cq*4);
            acc.x+=p.x; acc.y+=p.y; acc.z+=p.z; acc.w+=p.w;
        }
        float sv = sinv[h];
        *(float4*)(t_s + h*128 + cq*4) =
            make_float4(acc.x*sv, acc.y*sv, acc.z*sv, acc.w*sv);
    }
    __syncthreads();
    if(t<128){
        float o = (oacc + red[eO]) * sinv[hO];
        const float4* w2 = (const float4*)(Wa2 + (size_t)eO*128);
        const float4* th = (const float4*)(t_s + hO*128);
        #pragma unroll
        for(int cq=0;cq<32;cq++){
            float4 a=w2[cq], tv=th[cq];
            o += a.x*tv.x + a.y*tv.y + a.z*tv.z + a.w*tv.w;
        }
        xo[(size_t)rr*128 + eO] = qln[(size_t)rr*128 + eO] + o;
    }
}

// ------- k_ffn: LN2 + FFN + residual + mask (+ optional fused final LN) -------
__global__ void __launch_bounds__(512) k_ffn(
    const float* __restrict__ attin,
    const float* __restrict__ g2, const float* __restrict__ b2g,
    const float* __restrict__ W1, const float* __restrict__ b1,
    const float* __restrict__ W2, const float* __restrict__ b2,
    const unsigned char* __restrict__ msk, float* __restrict__ xo,
    const float* __restrict__ lnfg, const float* __restrict__ lnfb)
{
    __shared__ float xs[16][128];
    __shared__ float hs[16][128];
    __shared__ float ws[8192];
    int t = threadIdx.x; int e = t&127; int rg = t>>7; int l = t&31; int w = t>>5;
    int r0 = blockIdx.x*16;
    for(int k=t;k<2048;k+=512) xs[k>>7][k&127] = attin[(size_t)r0*Hq + k];
    __syncthreads();
    lnrow(xs[w], g2, b2g, l, (float*)0);
    __syncthreads();

    float o4[4];
    gemmv4(xs, ws, W1, b1, t, e, rg, o4);
    #pragma unroll
    for(int r=0;r<4;r++) hs[rg*4+r][e] = fmaxf(o4[r], 0.f);
    __syncthreads();
    gemmv4(hs, ws, W2, b2, t, e, rg, o4);
    if(lnfg == (const float*)0){
        #pragma unroll
        for(int r=0;r<4;r++){
            int row = r0 + rg*4 + r;
            float kp = msk[row] ? 0.f : 1.f;
            xo[(size_t)row*Hq + e] = (o4[r] + xs[rg*4+r][e]) * kp;
        }
    } else {
        #pragma unroll
        for(int r=0;r<4;r++){
            int rr = rg*4 + r;
            float kp = msk[r0+rr] ? 0.f : 1.f;
            float v = (o4[r] + xs[rr][e]) * kp;
            hs[rr][e] = v;
        }
        __syncthreads();
        lnrow(hs[w], lnfg, lnfb, l, xo + (size_t)(r0+w)*Hq);
    }
}

// ---------------- launch ----------------
extern "C" void kernel_launch(void* const* d_in, const int* in_sizes, int n_in,
                              void* d_out, int out_size){
    const float* seqs = (const float*)d_in[0];
    const unsigned char* msk = (const unsigned char*)d_in[1];
    const float* tm  = (const float*)d_in[2];
    const float* Qw  = (const float*)d_in[3];
    const float* Qb  = (const float*)d_in[4];
    const float* Kw  = (const float*)d_in[5];
    const float* Kb  = (const float*)d_in[6];
    const float* Vw  = (const float*)d_in[7];
    const float* Vb  = (const float*)d_in[8];
    const float* WA1 = (const float*)d_in[9];
    const float* WA2 = (const float*)d_in[10];
    const float* ln1g= (const float*)d_in[11];
    const float* ln1b= (const float*)d_in[12];
    const float* ln2g= (const float*)d_in[13];
    const float* ln2b= (const float*)d_in[14];
    const float* c1w = (const float*)d_in[15];
    const float* c1b = (const float*)d_in[16];
    const float* c2w = (const float*)d_in[17];
    const float* c2b = (const float*)d_in[18];
    const float* lnfg= (const float*)d_in[19];
    const float* lnfb= (const float*)d_in[20];

    float *gqln,*gQ,*gK,*gV,*gu,*gqk,*gatt,*gx;
    cudaGetSymbolAddress((void**)&gqln, g_qln);
    cudaGetSymbolAddress((void**)&gQ,   g_Q);
    cudaGetSymbolAddress((void**)&gK,   g_K);
    cudaGetSymbolAddress((void**)&gV,   g_V);
    cudaGetSymbolAddress((void**)&gu,   g_u);
    cudaGetSymbolAddress((void**)&gqk,  g_qk);
    cudaGetSymbolAddress((void**)&gatt, g_att);
    cudaGetSymbolAddress((void**)&gx,   g_x);

    cudaFuncSetAttribute(k_attn, cudaFuncAttributeMaxDynamicSharedMemorySize, ATTN_SMEM);

    for(int blk=0; blk<2; blk++){
        const float* xin = blk ? (const float*)gx : seqs;
        k_proj<<<128,512>>>(xin, ln1g+blk*Hq, ln1b+blk*Hq,
                            Qw+(size_t)blk*HHq, Qb+blk*Hq,
                            Kw+(size_t)blk*HHq, Kb+blk*Hq,
                            Vw+(size_t)blk*HHq, Vb+blk*Hq,
                            WA1+(size_t)blk*HHq,
                            gqln, gQ, gK, gV, gu);
        k_qk  <<<320,256>>>(gQ, gK, gqk);
        k_attn<<<BLq,256,ATTN_SMEM>>>(tm, gqln, gV, gu, gqk, msk,
                                      WA2+(size_t)blk*HHq, gatt);
        k_ffn <<<128,512>>>(gatt, ln2g+blk*Hq, ln2b+blk*Hq,
                            c1w+(size_t)blk*HHq, c1b+blk*Hq,
                            c2w+(size_t)blk*HHq, c2b+blk*Hq, msk,
                            blk==0 ? gx : (float*)d_out,
                            blk==0 ? (const float*)0 : lnfg,
                            blk==0 ? (const float*)0 : lnfb);
    }
}

// round 14
// speedup vs baseline: 2.3421x; 1.0171x over previous
#include <cuda_runtime.h>
#include <cstdint>

#define Hq 128
#define BLq 2048
#define HHq 16384
typedef unsigned long long ull;

// ---------------- scratch ----------------
__device__ float g_qln[BLq*Hq];
__device__ float g_Q  [BLq*Hq];
__device__ float g_K  [BLq*Hq];
__device__ float g_V  [BLq*Hq];
__device__ float g_u  [BLq*4*Hq];
__device__ float g_qk [BLq*4*256];
__device__ float g_att[BLq*Hq];
__device__ float g_x  [BLq*Hq];

// ---------------- helpers ----------------
__device__ __forceinline__ void cpa16(float* s, const float* g){
    unsigned sa = (unsigned)__cvta_generic_to_shared(s);
    asm volatile("cp.async.cg.shared.global [%0], [%1], 16;\n" :: "r"(sa), "l"(g));
}
__device__ __forceinline__ void ffma2(ull &acc, ull a, ull b){
    asm("fma.rn.f32x2 %0, %1, %2, %0;" : "+l"(acc) : "l"(a), "l"(b));
}
__device__ __forceinline__ float ullsum(ull v){
    float lo,hi; asm("mov.b64 {%0,%1}, %2;" : "=f"(lo), "=f"(hi) : "l"(v));
    return lo+hi;
}
__device__ __forceinline__ ull dup2(float a){
    ull r; asm("mov.b64 %0, {%1,%1};" : "=l"(r) : "f"(a)); return r;
}
__device__ __forceinline__ void unp2(ull v, float &a, float &b){
    asm("mov.b64 {%0,%1}, %2;" : "=f"(a), "=f"(b) : "l"(v));
}

// per-warp LN of one 128-float smem row (writes back; optional global copy)
__device__ __forceinline__ void lnrow(float* row, const float* __restrict__ g,
                                      const float* __restrict__ bb, int l,
                                      float* __restrict__ gout){
    float v0=row[l], v1=row[l+32], v2=row[l+64], v3=row[l+96];
    float s  = v0+v1+v2+v3;
    float s2 = v0*v0+v1*v1+v2*v2+v3*v3;
    #pragma unroll
    for(int o=16;o;o>>=1){
        s  += __shfl_xor_sync(0xffffffffu, s , o);
        s2 += __shfl_xor_sync(0xffffffffu, s2, o);
    }
    float m   = s * (1.0f/128.0f);
    float inv = rsqrtf(s2*(1.0f/128.0f) - m*m + 1e-8f);
    float o0 = (v0-m)*inv*g[l]    + bb[l];
    float o1 = (v1-m)*inv*g[l+32] + bb[l+32];
    float o2 = (v2-m)*inv*g[l+64] + bb[l+64];
    float o3 = (v3-m)*inv*g[l+96] + bb[l+96];
    row[l]=o0; row[l+32]=o1; row[l+64]=o2; row[l+96]=o3;
    if(gout){ gout[l]=o0; gout[l+32]=o1; gout[l+64]=o2; gout[l+96]=o3; }
}

// ---- gemmv4 (R13): W k-quarters staged via cp.async, double-buffered ----
__device__ __forceinline__ void gemmv4(const float (*xin)[128], float* ws,
                                       const float* __restrict__ W,
                                       const float* __restrict__ bias,
                                       int t, int e, int rg, float out[4]){
    ull acc[4];
    #pragma unroll
    for(int r=0;r<4;r++) acc[r]=0ULL;
    int sw = e&7;
    #pragma unroll
    for(int k=0;k<2;k++){
        int idx = t + k*512;
        int ee = idx>>3, c4 = idx&7;
        cpa16(ws + ee*32 + ((c4 ^ (ee&7))<<2), W + (size_t)ee*128 + c4*4);
    }
    asm volatile("cp.async.commit_group;\n"::);
    #pragma unroll
    for(int s=0;s<4;s++){
        if(s+1<4){
            float* wd = ws + ((s+1)&1)*4096;
            #pragma unroll
            for(int k=0;k<2;k++){
                int idx = t + k*512;
                int ee = idx>>3, c4 = idx&7;
                cpa16(wd + ee*32 + ((c4 ^ (ee&7))<<2),
                      W + (size_t)ee*128 + (s+1)*32 + c4*4);
            }
            asm volatile("cp.async.commit_group;\n"::);
            asm volatile("cp.async.wait_group 1;\n"::);
        } else {
            asm volatile("cp.async.wait_group 0;\n"::);
        }
        __syncthreads();
        const float* wsrc = ws + (s&1)*4096;
        #pragma unroll
        for(int cq=0;cq<8;cq++){
            ulonglong2 wv = *(const ulonglong2*)(wsrc + e*32 + ((cq ^ sw)<<2));
            #pragma unroll
            for(int r=0;r<4;r++){
                ulonglong2 xv = *(const ulonglong2*)(&xin[rg*4+r][s*32 + cq*4]);
                ffma2(acc[r], wv.x, xv.x);
                ffma2(acc[r], wv.y, xv.y);
            }
        }
        __syncthreads();
    }
    float be = bias[e];
    #pragma unroll
    for(int r=0;r<4;r++) out[r] = ullsum(acc[r]) + be;
}

// ---------------- k_proj: LN1 + Q,K,V + u = WA1_h^T Q_h ----------------
__global__ void __launch_bounds__(512) k_proj(
    const float* __restrict__ xin,
    const float* __restrict__ g1, const float* __restrict__ b1,
    const float* __restrict__ Wq, const float* __restrict__ bq,
    const float* __restrict__ Wk, const float* __restrict__ bk,
    const float* __restrict__ Wv, const float* __restrict__ bv,
    const float* __restrict__ Wa1,
    float* __restrict__ qlno,
    float* __restrict__ Qo, float* __restrict__ Ko, float* __restrict__ Vo,
    float* __restrict__ uo)
{
    __shared__ float xs[16][128];
    __shared__ float Qs[16][128];
    __shared__ float ws[8192];
    int t = threadIdx.x; int e = t&127; int rg = t>>7; int l = t&31; int w = t>>5;
    int r0 = blockIdx.x*16;
    for(int k=t;k<2048;k+=512) xs[k>>7][k&127] = xin[(size_t)r0*Hq + k];
    __syncthreads();
    lnrow(xs[w], g1, b1, l, qlno + (size_t)(r0+w)*Hq);
    __syncthreads();

    float o4[4];
    gemmv4(xs, ws, Wq, bq, t, e, rg, o4);
    #pragma unroll
    for(int r=0;r<4;r++){
        int rr = rg*4+r;
        Qo[(size_t)(r0+rr)*Hq+e]=o4[r]; Qs[rr][e]=o4[r];
    }
    gemmv4(xs, ws, Wk, bk, t, e, rg, o4);
    #pragma unroll
    for(int r=0;r<4;r++) Ko[(size_t)(r0+rg*4+r)*Hq+e]=o4[r];
    gemmv4(xs, ws, Wv, bv, t, e, rg, o4);
    #pragma unroll
    for(int r=0;r<4;r++) Vo[(size_t)(r0+rg*4+r)*Hq+e]=o4[r];
    __syncthreads();

    int h = rg, c = e;
    ull ua[16];
    #pragma unroll
    for(int r=0;r<16;r++) ua[r]=0ULL;
    const float* wbase = Wa1 + c;
    #pragma unroll 4
    for(int d=0; d<32; d+=2){
        float wa = wbase[(size_t)(h*32+d)*128];
        float wb = wbase[(size_t)(h*32+d+1)*128];
        ull w2; asm("mov.b64 %0, {%1,%2};" : "=l"(w2) : "f"(wa), "f"(wb));
        #pragma unroll
        for(int r=0;r<16;r++){
            ull q2 = *(const ull*)(&Qs[r][h*32+d]);
            ffma2(ua[r], w2, q2);
        }
    }
    #pragma unroll
    for(int r=0;r<16;r++)
        uo[((size_t)(r0+r)*4 + h)*128 + c] = ullsum(ua[r]);
}

// ---------------- k_qk: lower-triangle tiles only ----------------
__global__ void __launch_bounds__(256) k_qk(const float* __restrict__ Qp,
                                            const float* __restrict__ Kp,
                                            float* __restrict__ qko){
    __shared__ float Qsh[64*33];
    __shared__ float Ksh[64*33];
    const int ITt[10]={0,1,1,2,2,2,3,3,3,3};
    const int JTt[10]={0,0,1,0,1,2,0,1,2,3};
    int bid = blockIdx.x;
    int tri = bid%10; int h=(bid/10)&3; int b=bid/40;
    int it = ITt[tri], jt = JTt[tri];
    int t = threadIdx.x;
    int i0 = it*64, j0 = jt*64;
    for(int k=t;k<2048;k+=256){
        int rr=k>>5, dd=k&31;
        Qsh[rr*33+dd] = Qp[((size_t)(b*256+i0+rr))*128 + h*32+dd];
        Ksh[rr*33+dd] = Kp[((size_t)(b*256+j0+rr))*128 + h*32+dd];
    }
    __syncthreads();
    int i4 = (t>>4)<<2, j4 = (t&15)<<2;
    float acc[4][4];
    #pragma unroll
    for(int a=0;a<4;a++)
        #pragma unroll
        for(int bb=0;bb<4;bb++) acc[a][bb]=0.f;
    #pragma unroll 4
    for(int d=0; d<32; d++){
        float q0=Qsh[(i4+0)*33+d], q1=Qsh[(i4+1)*33+d], q2=Qsh[(i4+2)*33+d], q3=Qsh[(i4+3)*33+d];
        float k0=Ksh[(j4+0)*33+d], k1=Ksh[(j4+1)*33+d], k2=Ksh[(j4+2)*33+d], k3=Ksh[(j4+3)*33+d];
        acc[0][0]+=q0*k0; acc[0][1]+=q0*k1; acc[0][2]+=q0*k2; acc[0][3]+=q0*k3;
        acc[1][0]+=q1*k0; acc[1][1]+=q1*k1; acc[1][2]+=q1*k2; acc[1][3]+=q1*k3;
        acc[2][0]+=q2*k0; acc[2][1]+=q2*k1; acc[2][2]+=q2*k2; acc[2][3]+=q2*k3;
        acc[3][0]+=q3*k0; acc[3][1]+=q3*k1; acc[3][2]+=q3*k2; acc[3][3]+=q3*k3;
    }
    #pragma unroll
    for(int ii=0;ii<4;ii++){
        size_t base = ((size_t)(b*256 + i0+i4+ii)*4 + h)*256 + j0 + j4;
        *(float4*)(qko + base) = make_float4(acc[ii][0],acc[ii][1],acc[ii][2],acc[ii][3]);
    }
}

// ------ fused attention v3: 32-row chunks, ring-3, pipelined A(c)/C,O(c-1) ----
__device__ __forceinline__ void attn_load_chunk(float* dst, const float* src, int jn, int t){
    for(int k=t;k<jn*32;k+=256){
        int jr=k>>5, c4=k&31;
        cpa16(dst + jr*128 + ((c4 ^ (jr&7))<<2), src + 4*k);
    }
    for(int k=t;k<(32-jn)*32;k+=256)
        *(float4*)(dst + (jn+(k>>5))*128 + (k&31)*4) = make_float4(0.f,0.f,0.f,0.f);
}

__device__ __forceinline__ void attn_co(const float* bufp, const float* scp,
                                        const float* Vb, ull (&tacc)[4][2],
                                        float& oacc0, float& oacc1,
                                        int w, int l, int hO, int jhO){
    // O: w@V partials (independent LDGs issue first, C's FMAs cover latency)
    const float* wp = scp + hO*32 + jhO*16;
    #pragma unroll
    for(int jj=0;jj<8;jj++){
        oacc0 += wp[jj]   * Vb[jj*128];
        oacc1 += wp[8+jj] * Vb[(8+jj)*128];
    }
    // C: warp w owns j-quad w*4.., lane l owns float4-column l
    #pragma unroll
    for(int jj=0;jj<4;jj++){
        int j = (w<<2)+jj;
        ulonglong2 tv = *(const ulonglong2*)(bufp + j*128 + ((l ^ (j&7))<<2));
        ull w0=dup2(scp[j]), w1=dup2(scp[32+j]), w2=dup2(scp[64+j]), w3=dup2(scp[96+j]);
        ffma2(tacc[0][0],w0,tv.x); ffma2(tacc[0][1],w0,tv.y);
        ffma2(tacc[1][0],w1,tv.x); ffma2(tacc[1][1],w1,tv.y);
        ffma2(tacc[2][0],w2,tv.x); ffma2(tacc[2][1],w2,tv.y);
        ffma2(tacc[3][0],w3,tv.x); ffma2(tacc[3][1],w3,tv.y);
    }
}

// floats: buf 3x4096 | u 512 | s4 1024 | sc_w 2x128 | sinv 4
#define ATTN_FLOATS (12288 + 512 + 1024 + 256 + 4)
#define ATTN_SMEM (ATTN_FLOATS*4)
__global__ void __launch_bounds__(256) k_attn(
    const float* __restrict__ tm,  const float* __restrict__ qln,
    const float* __restrict__ Vp,  const float* __restrict__ up,
    const float* __restrict__ qkg, const unsigned char* __restrict__ msk,
    const float* __restrict__ Wa2, float* __restrict__ xo)
{
    extern __shared__ float sm[];
    float* u_s  = sm + 12288;
    float* s4   = sm + 12800;
    float* sc_w = sm + 13824;
    float* sinv = sm + 14080;

    int t = threadIdx.x, l = t&31, w = t>>5;
    int r = blockIdx.x, b = r>>8;
    int i = 255 - (r&255);               // heavy rows first
    int rr = (b<<8) + i;
    bool rowmask = msk[rr] != 0;
    int nj  = rowmask ? 256 : (i+1);
    int nch = (nj + 31) >> 5;
    const float* tmrow = tm + (size_t)rr*32768;
    const float NEGV = -4294967295.0f;
    const float SCL  = 0.17677669529663689f;

    int qA = t>>5, jA = t&31;                    // A: c-eighth x j
    int eO = t&127, jhO = t>>7, hO = (t&127)>>5; // O: elem x j-half

    // prologue: u + chunk0 (grp1) + chunk1 (grp2; empty if nch==1)
    if(t < 128) cpa16(u_s + t*4, up + (size_t)rr*512 + t*4);
    { int jn = nj<32?nj:32; attn_load_chunk(sm, tmrow, jn, t); }
    asm volatile("cp.async.commit_group;\n"::);
    if(nch>1){ int jn = nj-32; if(jn>32) jn=32; attn_load_chunk(sm+4096, tmrow+4096, jn, t); }
    asm volatile("cp.async.commit_group;\n"::);

    ull tacc[4][2];
    #pragma unroll
    for(int a=0;a<4;a++){ tacc[a][0]=0ULL; tacc[a][1]=0ULL; }
    float oacc0=0.f, oacc1=0.f, s_run=0.f;

    for(int c=0;c<nch;c++){
        int cb = c - (c/3)*3;
        float qv = 0.f;
        if(w<4) qv = __ldg(qkg + ((size_t)rr*4 + w)*256 + (c<<5) + l);
        // chunk c complete: normally depth-1 wait; last iter must drain (the
        // trailing empty groups complete out-of-order and break the count).
        if(c == nch-1) asm volatile("cp.async.wait_group 0;\n"::);
        else           asm volatile("cp.async.wait_group 1;\n"::);
        __syncthreads();
        const float* bufc = sm + cb*4096;

        // ---- A(c): partial scores, thread (qA c-eighth, jA) ----
        {
            const float* base = bufc + jA*128;
            int swz = jA&7;
            ull a0=0ULL,a1=0ULL,a2=0ULL,a3=0ULL;
            #pragma unroll
            for(int k=0;k<4;k++){
                int c4 = (qA<<2)+k;
                ulonglong2 tv = *(const ulonglong2*)(base + ((c4^swz)<<2));
                ulonglong2 u0 = *(const ulonglong2*)(u_s +       (c4<<2));
                ulonglong2 u1 = *(const ulonglong2*)(u_s + 128 + (c4<<2));
                ulonglong2 u2 = *(const ulonglong2*)(u_s + 256 + (c4<<2));
                ulonglong2 u3 = *(const ulonglong2*)(u_s + 384 + (c4<<2));
                ffma2(a0,u0.x,tv.x); ffma2(a0,u0.y,tv.y);
                ffma2(a1,u1.x,tv.x); ffma2(a1,u1.y,tv.y);
                ffma2(a2,u2.x,tv.x); ffma2(a2,u2.y,tv.y);
                ffma2(a3,u3.x,tv.x); ffma2(a3,u3.y,tv.y);
            }
            int sb = (qA<<2)*32 + jA;
            s4[sb     ] = ullsum(a0);
            s4[sb + 32] = ullsum(a1);
            s4[sb + 64] = ullsum(a2);
            s4[sb + 96] = ullsum(a3);
        }
        // ---- C(c-1) + O(c-1): disjoint from A, same barrier-free region ----
        if(c>0){
            const float* bufp = sm + ((c-1)%3)*4096;
            const float* scp  = sc_w + ((c-1)&1)*128;
            const float* Vb = Vp + ((((size_t)b<<8) + ((c-1)<<5) + jhO*16)*128) + eO;
            attn_co(bufp, scp, Vb, tacc, oacc0, oacc1, w, l, hO, jhO);
        }
        __syncthreads();
        // prefetch chunk c+2 into buf freed by C(c-1)
        if(c+2<nch){
            int j0n=(c+2)<<5; int jn=nj-j0n; if(jn>32) jn=32;
            attn_load_chunk(sm + ((c+2)%3)*4096, tmrow + j0n*128, jn, t);
        }
        asm volatile("cp.async.commit_group;\n"::);
        // ---- B(c): reduce + static-max softmax (warp w = head w) ----
        if(w<4){
            float rv = s4[(0+w)*32+l] + s4[(4+w)*32+l] + s4[(8+w)*32+l] + s4[(12+w)*32+l]
                     + s4[(16+w)*32+l] + s4[(20+w)*32+l] + s4[(24+w)*32+l] + s4[(28+w)*32+l];
            rv = (rv + qv)*SCL;
            int j = (c<<5)+l;
            rv = rowmask ? 0.f : (j < nj ? rv : NEGV);
            float ev = __expf(rv);
            sc_w[(c&1)*128 + w*32 + l] = ev;
            s_run += ev;
        }
    }
    __syncthreads();
    // final C/O for chunk nch-1
    {
        const float* bufp = sm + ((nch-1)%3)*4096;
        const float* scp  = sc_w + ((nch-1)&1)*128;
        const float* Vb = Vp + ((((size_t)b<<8) + ((nch-1)<<5) + jhO*16)*128) + eO;
        attn_co(bufp, scp, Vb, tacc, oacc0, oacc1, w, l, hO, jhO);
    }
    __syncthreads();

    // ---- epilogue ----
    float oacc = oacc0 + oacc1;
    if(w<4){
        float v = s_run;
        #pragma unroll
        for(int o=16;o;o>>=1) v += __shfl_xor_sync(0xffffffffu, v, o);
        if(l==0) sinv[w] = 1.0f / v;
    }
    float* P   = sm;          // bufs dead after final C/O + bar
    float* t_s = sm + 4096;
    float* red = sm + 8192;
    if(jhO==1) red[eO] = oacc;
    #pragma unroll
    for(int h=0;h<4;h++){
        float f0,f1,f2,f3;
        unp2(tacc[h][0], f0, f1);
        unp2(tacc[h][1], f2, f3);
        *(float4*)(P + w*512 + h*128 + (l<<2)) = make_float4(f0,f1,f2,f3);
    }
    __syncthreads();
    if(t<128){
        int h = t>>5, cq = t&31;
        float4 acc = make_float4(0.f,0.f,0.f,0.f);
        #pragma unroll
        for(int g=0;g<8;g++){
            float4 p = *(const float4*)(P + g*512 + h*128 + (cq<<2));
            acc.x+=p.x; acc.y+=p.y; acc.z+=p.z; acc.w+=p.w;
        }
        float sv = sinv[h];
        *(float4*)(t_s + h*128 + (cq<<2)) =
            make_float4(acc.x*sv, acc.y*sv, acc.z*sv, acc.w*sv);
    }
    __syncthreads();
    if(t<128){
        float o = (oacc + red[eO]) * sinv[hO];
        const float4* w2 = (const float4*)(Wa2 + (size_t)eO*128);
        const float4* th = (const float4*)(t_s + hO*128);
        #pragma unroll
        for(int cq=0;cq<32;cq++){
            float4 a=w2[cq], tv=th[cq];
            o += a.x*tv.x + a.y*tv.y + a.z*tv.z + a.w*tv.w;
        }
        xo[(size_t)rr*128 + eO] = qln[(size_t)rr*128 + eO] + o;
    }
}

// ------- k_ffn: LN2 + FFN + residual + mask (+ optional fused final LN) -------
__global__ void __launch_bounds__(512) k_ffn(
    const float* __restrict__ attin,
    const float* __restrict__ g2, const float* __restrict__ b2g,
    const float* __restrict__ W1, const float* __restrict__ b1,
    const float* __restrict__ W2, const float* __restrict__ b2,
    const unsigned char* __restrict__ msk, float* __restrict__ xo,
    const float* __restrict__ lnfg, const float* __restrict__ lnfb)
{
    __shared__ float xs[16][128];
    __shared__ float hs[16][128];
    __shared__ float ws[8192];
    int t = threadIdx.x; int e = t&127; int rg = t>>7; int l = t&31; int w = t>>5;
    int r0 = blockIdx.x*16;
    for(int k=t;k<2048;k+=512) xs[k>>7][k&127] = attin[(size_t)r0*Hq + k];
    __syncthreads();
    lnrow(xs[w], g2, b2g, l, (float*)0);
    __syncthreads();

    float o4[4];
    gemmv4(xs, ws, W1, b1, t, e, rg, o4);
    #pragma unroll
    for(int r=0;r<4;r++) hs[rg*4+r][e] = fmaxf(o4[r], 0.f);
    __syncthreads();
    gemmv4(hs, ws, W2, b2, t, e, rg, o4);
    if(lnfg == (const float*)0){
        #pragma unroll
        for(int r=0;r<4;r++){
            int row = r0 + rg*4 + r;
            float kp = msk[row] ? 0.f : 1.f;
            xo[(size_t)row*Hq + e] = (o4[r] + xs[rg*4+r][e]) * kp;
        }
    } else {
        #pragma unroll
        for(int r=0;r<4;r++){
            int rr = rg*4 + r;
            float kp = msk[r0+rr] ? 0.f : 1.f;
            float v = (o4[r] + xs[rr][e]) * kp;
            hs[rr][e] = v;
        }
        __syncthreads();
        lnrow(hs[w], lnfg, lnfb, l, xo + (size_t)(r0+w)*Hq);
    }
}

// ---------------- launch ----------------
extern "C" void kernel_launch(void* const* d_in, const int* in_sizes, int n_in,
                              void* d_out, int out_size){
    const float* seqs = (const float*)d_in[0];
    const unsigned char* msk = (const unsigned char*)d_in[1];
    const float* tm  = (const float*)d_in[2];
    const float* Qw  = (const float*)d_in[3];
    const float* Qb  = (const float*)d_in[4];
    const float* Kw  = (const float*)d_in[5];
    const float* Kb  = (const float*)d_in[6];
    const float* Vw  = (const float*)d_in[7];
    const float* Vb  = (const float*)d_in[8];
    const float* WA1 = (const float*)d_in[9];
    const float* WA2 = (const float*)d_in[10];
    const float* ln1g= (const float*)d_in[11];
    const float* ln1b= (const float*)d_in[12];
    const float* ln2g= (const float*)d_in[13];
    const float* ln2b= (const float*)d_in[14];
    const float* c1w = (const float*)d_in[15];
    const float* c1b = (const float*)d_in[16];
    const float* c2w = (const float*)d_in[17];
    const float* c2b = (const float*)d_in[18];
    const float* lnfg= (const float*)d_in[19];
    const float* lnfb= (const float*)d_in[20];

    float *gqln,*gQ,*gK,*gV,*gu,*gqk,*gatt,*gx;
    cudaGetSymbolAddress((void**)&gqln, g_qln);
    cudaGetSymbolAddress((void**)&gQ,   g_Q);
    cudaGetSymbolAddress((void**)&gK,   g_K);
    cudaGetSymbolAddress((void**)&gV,   g_V);
    cudaGetSymbolAddress((void**)&gu,   g_u);
    cudaGetSymbolAddress((void**)&gqk,  g_qk);
    cudaGetSymbolAddress((void**)&gatt, g_att);
    cudaGetSymbolAddress((void**)&gx,   g_x);

    cudaFuncSetAttribute(k_attn, cudaFuncAttributeMaxDynamicSharedMemorySize, ATTN_SMEM);

    for(int blk=0; blk<2; blk++){
        const float* xin = blk ? (const float*)gx : seqs;
        k_proj<<<128,512>>>(xin, ln1g+blk*Hq, ln1b+blk*Hq,
                            Qw+(size_t)blk*HHq, Qb+blk*Hq,
                            Kw+(size_t)blk*HHq, Kb+blk*Hq,
                            Vw+(size_t)blk*HHq, Vb+blk*Hq,
                            WA1+(size_t)blk*HHq,
                            gqln, gQ, gK, gV, gu);
        k_qk  <<<320,256>>>(gQ, gK, gqk);
        k_attn<<<BLq,256,ATTN_SMEM>>>(tm, gqln, gV, gu, gqk, msk,
                                      WA2+(size_t)blk*HHq, gatt);
        k_ffn <<<128,512>>>(gatt, ln2g+blk*Hq, ln2b+blk*Hq,
                            c1w+(size_t)blk*HHq, c1b+blk*Hq,
                            c2w+(size_t)blk*HHq, c2b+blk*Hq, msk,
                            blk==0 ? gx : (float*)d_out,
                            blk==0 ? (const float*)0 : lnfg,
                            blk==0 ? (const float*)0 : lnfb);
    }
}

// round 17
// speedup vs baseline: 2.7369x; 1.1686x over previous
#include <cuda_runtime.h>
#include <cstdint>

#define Hq 128
#define BLq 2048
#define HHq 16384
typedef unsigned long long ull;

// ---------------- scratch ----------------
__device__ float g_qln[BLq*Hq];
__device__ float g_Q  [BLq*Hq];
__device__ float g_K  [BLq*Hq];
__device__ float g_V  [BLq*Hq];
__device__ float g_u  [BLq*4*Hq];
__device__ float g_qk [BLq*4*256];
__device__ float g_att[BLq*Hq];
__device__ float g_x  [BLq*Hq];

// ---------------- helpers ----------------
__device__ __forceinline__ void cpa16(float* s, const float* g){
    unsigned sa = (unsigned)__cvta_generic_to_shared(s);
    asm volatile("cp.async.cg.shared.global [%0], [%1], 16;\n" :: "r"(sa), "l"(g));
}
__device__ __forceinline__ void ffma2(ull &acc, ull a, ull b){
    asm("fma.rn.f32x2 %0, %1, %2, %0;" : "+l"(acc) : "l"(a), "l"(b));
}
__device__ __forceinline__ float ullsum(ull v){
    float lo,hi; asm("mov.b64 {%0,%1}, %2;" : "=f"(lo), "=f"(hi) : "l"(v));
    return lo+hi;
}
__device__ __forceinline__ ull dup2(float a){
    ull r; asm("mov.b64 %0, {%1,%1};" : "=l"(r) : "f"(a)); return r;
}
__device__ __forceinline__ void unp2(ull v, float &a, float &b){
    asm("mov.b64 {%0,%1}, %2;" : "=f"(a), "=f"(b) : "l"(v));
}

// per-warp LN of one 128-float smem row (writes back; optional global copy)
__device__ __forceinline__ void lnrow(float* row, const float* __restrict__ g,
                                      const float* __restrict__ bb, int l,
                                      float* __restrict__ gout){
    float v0=row[l], v1=row[l+32], v2=row[l+64], v3=row[l+96];
    float s  = v0+v1+v2+v3;
    float s2 = v0*v0+v1*v1+v2*v2+v3*v3;
    #pragma unroll
    for(int o=16;o;o>>=1){
        s  += __shfl_xor_sync(0xffffffffu, s , o);
        s2 += __shfl_xor_sync(0xffffffffu, s2, o);
    }
    float m   = s * (1.0f/128.0f);
    float inv = rsqrtf(s2*(1.0f/128.0f) - m*m + 1e-8f);
    float o0 = (v0-m)*inv*g[l]    + bb[l];
    float o1 = (v1-m)*inv*g[l+32] + bb[l+32];
    float o2 = (v2-m)*inv*g[l+64] + bb[l+64];
    float o3 = (v3-m)*inv*g[l+96] + bb[l+96];
    row[l]=o0; row[l+32]=o1; row[l+64]=o2; row[l+96]=o3;
    if(gout){ gout[l]=o0; gout[l+32]=o1; gout[l+64]=o2; gout[l+96]=o3; }
}

// ---- gemmv5: 8-row tile, 128 threads, full K per thread, staged W ----
// thread e owns out[e] for all 8 rows. W quarters cp.async double-buffered.
__device__ __forceinline__ void gemmv5(const float (*xin)[128], float* ws,
                                       const float* __restrict__ W,
                                       const float* __restrict__ bias,
                                       int t, float out[8]){
    int e = t;
    ull acc[8];
    #pragma unroll
    for(int r=0;r<8;r++) acc[r]=0ULL;
    int sw = e&7;
    #pragma unroll
    for(int k=0;k<8;k++){
        int idx = t + k*128;
        int ee = idx>>3, c4 = idx&7;
        cpa16(ws + ee*32 + ((c4 ^ (ee&7))<<2), W + (size_t)ee*128 + c4*4);
    }
    asm volatile("cp.async.commit_group;\n"::);
    #pragma unroll
    for(int s=0;s<4;s++){
        if(s+1<4){
            float* wd = ws + ((s+1)&1)*4096;
            #pragma unroll
            for(int k=0;k<8;k++){
                int idx = t + k*128;
                int ee = idx>>3, c4 = idx&7;
                cpa16(wd + ee*32 + ((c4 ^ (ee&7))<<2),
                      W + (size_t)ee*128 + (s+1)*32 + c4*4);
            }
            asm volatile("cp.async.commit_group;\n"::);
            asm volatile("cp.async.wait_group 1;\n"::);
        } else {
            asm volatile("cp.async.wait_group 0;\n"::);
        }
        __syncthreads();
        const float* wsrc = ws + (s&1)*4096;
        #pragma unroll
        for(int cq=0;cq<8;cq++){
            ulonglong2 wv = *(const ulonglong2*)(wsrc + e*32 + ((cq ^ sw)<<2));
            #pragma unroll
            for(int r=0;r<8;r++){
                ulonglong2 xv = *(const ulonglong2*)(&xin[r][s*32 + cq*4]);
                ffma2(acc[r], wv.x, xv.x);
                ffma2(acc[r], wv.y, xv.y);
            }
        }
        __syncthreads();
    }
    float be = bias[e];
    #pragma unroll
    for(int r=0;r<8;r++) out[r] = ullsum(acc[r]) + be;
}

// ---------------- k_proj: LN1 + Q,K,V + u = WA1_h^T Q_h (8-row tile) --------
__global__ void __launch_bounds__(128) k_proj(
    const float* __restrict__ xin,
    const float* __restrict__ g1, const float* __restrict__ b1,
    const float* __restrict__ Wq, const float* __restrict__ bq,
    const float* __restrict__ Wk, const float* __restrict__ bk,
    const float* __restrict__ Wv, const float* __restrict__ bv,
    const float* __restrict__ Wa1,
    float* __restrict__ qlno,
    float* __restrict__ Qo, float* __restrict__ Ko, float* __restrict__ Vo,
    float* __restrict__ uo)
{
    __shared__ float xs[8][128];
    __shared__ float Qs[8][128];
    __shared__ float ws[8192];
    int t = threadIdx.x; int e = t; int l = t&31; int w = t>>5;
    int r0 = blockIdx.x*8;
    #pragma unroll
    for(int k=0;k<8;k++) xs[k][e] = xin[(size_t)(r0+k)*Hq + e];
    __syncthreads();
    lnrow(xs[w],   g1, b1, l, qlno + (size_t)(r0+w)*Hq);
    lnrow(xs[w+4], g1, b1, l, qlno + (size_t)(r0+w+4)*Hq);
    __syncthreads();

    float o8[8];
    gemmv5(xs, ws, Wq, bq, t, o8);
    #pragma unroll
    for(int r=0;r<8;r++){ Qo[(size_t)(r0+r)*Hq+e]=o8[r]; Qs[r][e]=o8[r]; }
    gemmv5(xs, ws, Wk, bk, t, o8);
    #pragma unroll
    for(int r=0;r<8;r++) Ko[(size_t)(r0+r)*Hq+e]=o8[r];
    gemmv5(xs, ws, Wv, bv, t, o8);
    #pragma unroll
    for(int r=0;r<8;r++) Vo[(size_t)(r0+r)*Hq+e]=o8[r];
    __syncthreads();

    // u[row][h][e] = sum_d WA1[h*32+d, e] * Q[row, h*32+d]
    const float* wbase = Wa1 + e;
    #pragma unroll
    for(int h=0;h<4;h++){
        ull ua[8];
        #pragma unroll
        for(int r=0;r<8;r++) ua[r]=0ULL;
        #pragma unroll 4
        for(int d=0; d<32; d+=2){
            float wa = wbase[(size_t)(h*32+d)*128];
            float wb = wbase[(size_t)(h*32+d+1)*128];
            ull w2; asm("mov.b64 %0, {%1,%2};" : "=l"(w2) : "f"(wa), "f"(wb));
            #pragma unroll
            for(int r=0;r<8;r++){
                ull q2 = *(const ull*)(&Qs[r][h*32+d]);
                ffma2(ua[r], w2, q2);
            }
        }
        #pragma unroll
        for(int r=0;r<8;r++)
            uo[((size_t)(r0+r)*4 + h)*128 + e] = ullsum(ua[r]);
    }
}

// ---------------- k_qk: lower-triangle tiles only ----------------
__global__ void __launch_bounds__(256) k_qk(const float* __restrict__ Qp,
                                            const float* __restrict__ Kp,
                                            float* __restrict__ qko){
    __shared__ float Qsh[64*33];
    __shared__ float Ksh[64*33];
    const int ITt[10]={0,1,1,2,2,2,3,3,3,3};
    const int JTt[10]={0,0,1,0,1,2,0,1,2,3};
    int bid = blockIdx.x;
    int tri = bid%10; int h=(bid/10)&3; int b=bid/40;
    int it = ITt[tri], jt = JTt[tri];
    int t = threadIdx.x;
    int i0 = it*64, j0 = jt*64;
    for(int k=t;k<2048;k+=256){
        int rr=k>>5, dd=k&31;
        Qsh[rr*33+dd] = Qp[((size_t)(b*256+i0+rr))*128 + h*32+dd];
        Ksh[rr*33+dd] = Kp[((size_t)(b*256+j0+rr))*128 + h*32+dd];
    }
    __syncthreads();
    int i4 = (t>>4)<<2, j4 = (t&15)<<2;
    float acc[4][4];
    #pragma unroll
    for(int a=0;a<4;a++)
        #pragma unroll
        for(int bb=0;bb<4;bb++) acc[a][bb]=0.f;
    #pragma unroll 4
    for(int d=0; d<32; d++){
        float q0=Qsh[(i4+0)*33+d], q1=Qsh[(i4+1)*33+d], q2=Qsh[(i4+2)*33+d], q3=Qsh[(i4+3)*33+d];
        float k0=Ksh[(j4+0)*33+d], k1=Ksh[(j4+1)*33+d], k2=Ksh[(j4+2)*33+d], k3=Ksh[(j4+3)*33+d];
        acc[0][0]+=q0*k0; acc[0][1]+=q0*k1; acc[0][2]+=q0*k2; acc[0][3]+=q0*k3;
        acc[1][0]+=q1*k0; acc[1][1]+=q1*k1; acc[1][2]+=q1*k2; acc[1][3]+=q1*k3;
        acc[2][0]+=q2*k0; acc[2][1]+=q2*k1; acc[2][2]+=q2*k2; acc[2][3]+=q2*k3;
        acc[3][0]+=q3*k0; acc[3][1]+=q3*k1; acc[3][2]+=q3*k2; acc[3][3]+=q3*k3;
    }
    #pragma unroll
    for(int ii=0;ii<4;ii++){
        size_t base = ((size_t)(b*256 + i0+i4+ii)*4 + h)*256 + j0 + j4;
        *(float4*)(qko + base) = make_float4(acc[ii][0],acc[ii][1],acc[ii][2],acc[ii][3]);
    }
}

// ------ fused attention v3: 32-row chunks, ring-3, pipelined A(c)/C,O(c-1) ----
__device__ __forceinline__ void attn_load_chunk(float* dst, const float* src, int jn, int t){
    for(int k=t;k<jn*32;k+=256){
        int jr=k>>5, c4=k&31;
        cpa16(dst + jr*128 + ((c4 ^ (jr&7))<<2), src + 4*k);
    }
    for(int k=t;k<(32-jn)*32;k+=256)
        *(float4*)(dst + (jn+(k>>5))*128 + (k&31)*4) = make_float4(0.f,0.f,0.f,0.f);
}

__device__ __forceinline__ void attn_co(const float* bufp, const float* scp,
                                        const float* Vb, ull (&tacc)[4][2],
                                        float& oacc0, float& oacc1,
                                        int w, int l, int hO, int jhO){
    const float* wp = scp + hO*32 + jhO*16;
    #pragma unroll
    for(int jj=0;jj<8;jj++){
        oacc0 += wp[jj]   * Vb[jj*128];
        oacc1 += wp[8+jj] * Vb[(8+jj)*128];
    }
    #pragma unroll
    for(int jj=0;jj<4;jj++){
        int j = (w<<2)+jj;
        ulonglong2 tv = *(const ulonglong2*)(bufp + j*128 + ((l ^ (j&7))<<2));
        ull w0=dup2(scp[j]), w1=dup2(scp[32+j]), w2=dup2(scp[64+j]), w3=dup2(scp[96+j]);
        ffma2(tacc[0][0],w0,tv.x); ffma2(tacc[0][1],w0,tv.y);
        ffma2(tacc[1][0],w1,tv.x); ffma2(tacc[1][1],w1,tv.y);
        ffma2(tacc[2][0],w2,tv.x); ffma2(tacc[2][1],w2,tv.y);
        ffma2(tacc[3][0],w3,tv.x); ffma2(tacc[3][1],w3,tv.y);
    }
}

// floats: buf 3x4096 | u 512 | s4 1024 | sc_w 2x128 | sinv 4
#define ATTN_FLOATS (12288 + 512 + 1024 + 256 + 4)
#define ATTN_SMEM (ATTN_FLOATS*4)
__global__ void __launch_bounds__(256) k_attn(
    const float* __restrict__ tm,  const float* __restrict__ qln,
    const float* __restrict__ Vp,  const float* __restrict__ up,
    const float* __restrict__ qkg, const unsigned char* __restrict__ msk,
    const float* __restrict__ Wa2, float* __restrict__ xo)
{
    extern __shared__ float sm[];
    float* u_s  = sm + 12288;
    float* s4   = sm + 12800;
    float* sc_w = sm + 13824;
    float* sinv = sm + 14080;

    int t = threadIdx.x, l = t&31, w = t>>5;
    int r = blockIdx.x, b = r>>8;
    int i = 255 - (r&255);               // heavy rows first
    int rr = (b<<8) + i;
    bool rowmask = msk[rr] != 0;
    int nj  = rowmask ? 256 : (i+1);
    int nch = (nj + 31) >> 5;
    const float* tmrow = tm + (size_t)rr*32768;
    const float NEGV = -4294967295.0f;
    const float SCL  = 0.17677669529663689f;

    int qA = t>>5, jA = t&31;
    int eO = t&127, jhO = t>>7, hO = (t&127)>>5;

    if(t < 128) cpa16(u_s + t*4, up + (size_t)rr*512 + t*4);
    { int jn = nj<32?nj:32; attn_load_chunk(sm, tmrow, jn, t); }
    asm volatile("cp.async.commit_group;\n"::);
    if(nch>1){ int jn = nj-32; if(jn>32) jn=32; attn_load_chunk(sm+4096, tmrow+4096, jn, t); }
    asm volatile("cp.async.commit_group;\n"::);

    ull tacc[4][2];
    #pragma unroll
    for(int a=0;a<4;a++){ tacc[a][0]=0ULL; tacc[a][1]=0ULL; }
    float oacc0=0.f, oacc1=0.f, s_run=0.f;

    for(int c=0;c<nch;c++){
        int cb = c - (c/3)*3;
        float qv = 0.f;
        if(w<4) qv = __ldg(qkg + ((size_t)rr*4 + w)*256 + (c<<5) + l);
        if(c == nch-1) asm volatile("cp.async.wait_group 0;\n"::);
        else           asm volatile("cp.async.wait_group 1;\n"::);
        __syncthreads();
        const float* bufc = sm + cb*4096;

        // ---- A(c) ----
        {
            const float* base = bufc + jA*128;
            int swz = jA&7;
            ull a0=0ULL,a1=0ULL,a2=0ULL,a3=0ULL;
            #pragma unroll
            for(int k=0;k<4;k++){
                int c4 = (qA<<2)+k;
                ulonglong2 tv = *(const ulonglong2*)(base + ((c4^swz)<<2));
                ulonglong2 u0 = *(const ulonglong2*)(u_s +       (c4<<2));
                ulonglong2 u1 = *(const ulonglong2*)(u_s + 128 + (c4<<2));
                ulonglong2 u2 = *(const ulonglong2*)(u_s + 256 + (c4<<2));
                ulonglong2 u3 = *(const ulonglong2*)(u_s + 384 + (c4<<2));
                ffma2(a0,u0.x,tv.x); ffma2(a0,u0.y,tv.y);
                ffma2(a1,u1.x,tv.x); ffma2(a1,u1.y,tv.y);
                ffma2(a2,u2.x,tv.x); ffma2(a2,u2.y,tv.y);
                ffma2(a3,u3.x,tv.x); ffma2(a3,u3.y,tv.y);
            }
            int sb = (qA<<2)*32 + jA;
            s4[sb     ] = ullsum(a0);
            s4[sb + 32] = ullsum(a1);
            s4[sb + 64] = ullsum(a2);
            s4[sb + 96] = ullsum(a3);
        }
        // ---- C(c-1)+O(c-1) ----
        if(c>0){
            const float* bufp = sm + ((c-1)%3)*4096;
            const float* scp  = sc_w + ((c-1)&1)*128;
            const float* Vb = Vp + ((((size_t)b<<8) + ((c-1)<<5) + jhO*16)*128) + eO;
            attn_co(bufp, scp, Vb, tacc, oacc0, oacc1, w, l, hO, jhO);
        }
        __syncthreads();
        if(c+2<nch){
            int j0n=(c+2)<<5; int jn=nj-j0n; if(jn>32) jn=32;
            attn_load_chunk(sm + ((c+2)%3)*4096, tmrow + j0n*128, jn, t);
        }
        asm volatile("cp.async.commit_group;\n"::);
        // ---- B(c) ----
        if(w<4){
            float rv = s4[(0+w)*32+l] + s4[(4+w)*32+l] + s4[(8+w)*32+l] + s4[(12+w)*32+l]
                     + s4[(16+w)*32+l] + s4[(20+w)*32+l] + s4[(24+w)*32+l] + s4[(28+w)*32+l];
            rv = (rv + qv)*SCL;
            int j = (c<<5)+l;
            rv = rowmask ? 0.f : (j < nj ? rv : NEGV);
            float ev = __expf(rv);
            sc_w[(c&1)*128 + w*32 + l] = ev;
            s_run += ev;
        }
    }
    __syncthreads();
    {
        const float* bufp = sm + ((nch-1)%3)*4096;
        const float* scp  = sc_w + ((nch-1)&1)*128;
        const float* Vb = Vp + ((((size_t)b<<8) + ((nch-1)<<5) + jhO*16)*128) + eO;
        attn_co(bufp, scp, Vb, tacc, oacc0, oacc1, w, l, hO, jhO);
    }
    __syncthreads();

    // ---- epilogue (warp-cooperative Wa2 GEMM) ----
    float* P    = sm;          // 8x512 tacc partials
    float* t_s  = sm + 4096;   // 512
    float* osum = sm + 8192;   // 256
    if(w<4){
        float v = s_run;
        #pragma unroll
        for(int o=16;o;o>>=1) v += __shfl_xor_sync(0xffffffffu, v, o);
        if(l==0) sinv[w] = 1.0f / v;
    }
    osum[t] = oacc0 + oacc1;
    #pragma unroll
    for(int h=0;h<4;h++){
        float f0,f1,f2,f3;
        unp2(tacc[h][0], f0, f1);
        unp2(tacc[h][1], f2, f3);
        *(float4*)(P + w*512 + h*128 + (l<<2)) = make_float4(f0,f1,f2,f3);
    }
    __syncthreads();
    if(t<128){
        int h = t>>5, cq = t&31;
        float4 acc = make_float4(0.f,0.f,0.f,0.f);
        #pragma unroll
        for(int g=0;g<8;g++){
            float4 p = *(const float4*)(P + g*512 + h*128 + (cq<<2));
            acc.x+=p.x; acc.y+=p.y; acc.z+=p.z; acc.w+=p.w;
        }
        float sv = sinv[h];
        *(float4*)(t_s + h*128 + (cq<<2)) =
            make_float4(acc.x*sv, acc.y*sv, acc.z*sv, acc.w*sv);
    }
    __syncthreads();
    // warp w covers e in [w*16, w*16+16); lanes parallel over columns
    {
        int e0 = w*16;
        #pragma unroll
        for(int k=0;k<16;k++){
            int e = e0 + k; int h = e>>5;
            const float* wr = Wa2 + (size_t)e*128;
            const float* th = t_s + h*128;
            float p = wr[l]*th[l] + wr[l+32]*th[l+32]
                    + wr[l+64]*th[l+64] + wr[l+96]*th[l+96];
            #pragma unroll
            for(int o=16;o;o>>=1) p += __shfl_xor_sync(0xffffffffu, p, o);
            if(l==0){
                float ov = (osum[e] + osum[e+128]) * sinv[h];
                xo[(size_t)rr*128 + e] = qln[(size_t)rr*128 + e] + ov + p;
            }
        }
    }
}

// ------- k_ffn: LN2 + FFN + residual + mask (+ optional fused final LN) -------
__global__ void __launch_bounds__(128) k_ffn(
    const float* __restrict__ attin,
    const float* __restrict__ g2, const float* __restrict__ b2g,
    const float* __restrict__ W1, const float* __restrict__ b1,
    const float* __restrict__ W2, const float* __restrict__ b2,
    const unsigned char* __restrict__ msk, float* __restrict__ xo,
    const float* __restrict__ lnfg, const float* __restrict__ lnfb)
{
    __shared__ float xs[8][128];
    __shared__ float hs[8][128];
    __shared__ float ws[8192];
    int t = threadIdx.x; int e = t; int l = t&31; int w = t>>5;
    int r0 = blockIdx.x*8;
    #pragma unroll
    for(int k=0;k<8;k++) xs[k][e] = attin[(size_t)(r0+k)*Hq + e];
    __syncthreads();
    lnrow(xs[w],   g2, b2g, l, (float*)0);
    lnrow(xs[w+4], g2, b2g, l, (float*)0);
    __syncthreads();

    float o8[8];
    gemmv5(xs, ws, W1, b1, t, o8);
    #pragma unroll
    for(int r=0;r<8;r++) hs[r][e] = fmaxf(o8[r], 0.f);
    __syncthreads();
    gemmv5(hs, ws, W2, b2, t, o8);
    if(lnfg == (const float*)0){
        #pragma unroll
        for(int r=0;r<8;r++){
            int row = r0 + r;
            float kp = msk[row] ? 0.f : 1.f;
            xo[(size_t)row*Hq + e] = (o8[r] + xs[r][e]) * kp;
        }
    } else {
        #pragma unroll
        for(int r=0;r<8;r++){
            float kp = msk[r0+r] ? 0.f : 1.f;
            hs[r][e] = (o8[r] + xs[r][e]) * kp;
        }
        __syncthreads();
        lnrow(hs[w],   lnfg, lnfb, l, xo + (size_t)(r0+w)*Hq);
        lnrow(hs[w+4], lnfg, lnfb, l, xo + (size_t)(r0+w+4)*Hq);
    }
}

// ---------------- launch ----------------
extern "C" void kernel_launch(void* const* d_in, const int* in_sizes, int n_in,
                              void* d_out, int out_size){
    const float* seqs = (const float*)d_in[0];
    const unsigned char* msk = (const unsigned char*)d_in[1];
    const float* tm  = (const float*)d_in[2];
    const float* Qw  = (const float*)d_in[3];
    const float* Qb  = (const float*)d_in[4];
    const float* Kw  = (const float*)d_in[5];
    const float* Kb  = (const float*)d_in[6];
    const float* Vw  = (const float*)d_in[7];
    const float* Vb  = (const float*)d_in[8];
    const float* WA1 = (const float*)d_in[9];
    const float* WA2 = (const float*)d_in[10];
    const float* ln1g= (const float*)d_in[11];
    const float* ln1b= (const float*)d_in[12];
    const float* ln2g= (const float*)d_in[13];
    const float* ln2b= (const float*)d_in[14];
    const float* c1w = (const float*)d_in[15];
    const float* c1b = (const float*)d_in[16];
    const float* c2w = (const float*)d_in[17];
    const float* c2b = (const float*)d_in[18];
    const float* lnfg= (const float*)d_in[19];
    const float* lnfb= (const float*)d_in[20];

    float *gqln,*gQ,*gK,*gV,*gu,*gqk,*gatt,*gx;
    cudaGetSymbolAddress((void**)&gqln, g_qln);
    cudaGetSymbolAddress((void**)&gQ,   g_Q);
    cudaGetSymbolAddress((void**)&gK,   g_K);
    cudaGetSymbolAddress((void**)&gV,   g_V);
    cudaGetSymbolAddress((void**)&gu,   g_u);
    cudaGetSymbolAddress((void**)&gqk,  g_qk);
    cudaGetSymbolAddress((void**)&gatt, g_att);
    cudaGetSymbolAddress((void**)&gx,   g_x);

    cudaFuncSetAttribute(k_attn, cudaFuncAttributeMaxDynamicSharedMemorySize, ATTN_SMEM);

    for(int blk=0; blk<2; blk++){
        const float* xin = blk ? (const float*)gx : seqs;
        k_proj<<<256,128>>>(xin, ln1g+blk*Hq, ln1b+blk*Hq,
                            Qw+(size_t)blk*HHq, Qb+blk*Hq,
                            Kw+(size_t)blk*HHq, Kb+blk*Hq,
                            Vw+(size_t)blk*HHq, Vb+blk*Hq,
                            WA1+(size_t)blk*HHq,
                            gqln, gQ, gK, gV, gu);
        k_qk  <<<320,256>>>(gQ, gK, gqk);
        k_attn<<<BLq,256,ATTN_SMEM>>>(tm, gqln, gV, gu, gqk, msk,
                                      WA2+(size_t)blk*HHq, gatt);
        k_ffn <<<256,128>>>(gatt, ln2g+blk*Hq, ln2b+blk*Hq,
                            c1w+(size_t)blk*HHq, c1b+blk*Hq,
                            c2w+(size_t)blk*HHq, c2b+blk*Hq, msk,
                            blk==0 ? gx : (float*)d_out,
                            blk==0 ? (const float*)0 : lnfg,
                            blk==0 ? (const float*)0 : lnfb);
    }
}